// round 16
// baseline (speedup 1.0000x reference)
#include <cuda_runtime.h>
#include <cuda_fp16.h>
#include <cstdint>

// R16 = third bench attempt of the R14 merge: R14 and R15 both failed at GB300
// container acquisition (infra outage; source never compiled/executed).
// Functionally identical to R14. Fallback if this also fails on infra: revert
// to the R13-passing source next round.

#define SEQ 2048
#define NB 4
#define NH 16
#define HD 64
#define HID 1024
#define MTOT (NB*SEQ)
#define NEG -1e30f
#define ATT_SCALE 0.125f

// ---------------- scratch (device globals; allocation-free rule) ----------
// dense [MTOT, HID] layouts: row = b*SEQ + s, col = h*HD + d
__device__ __half q_d[(size_t)MTOT*HID];
__device__ __half k_d[(size_t)MTOT*HID];
__device__ __half v_d[(size_t)MTOT*HID];
__device__ __half att_d[(size_t)MTOT*HID];
__device__ __half x_h[(size_t)MTOT*HID];
__device__ __half w_h[4*(size_t)HID*HID];

// ---------------- helpers -------------------------------------------------
__device__ __forceinline__ uint32_t smem_u32(const void* p){
    uint32_t a;
    asm("{ .reg .u64 t; cvta.to.shared.u64 t, %1; cvt.u32.u64 %0, t; }" : "=r"(a) : "l"(p));
    return a;
}
#define SWZ(b) ((b) ^ (((b) >> 3) & 0x70))

__device__ __forceinline__ void cp16s(uint32_t saddr, const void* g){
    asm volatile("cp.async.cg.shared.global [%0], [%1], 16;\n" :: "r"(saddr), "l"(g));
}
__device__ __forceinline__ void cp16z(uint32_t saddr, const void* g, int pred){
    int sz = pred ? 16 : 0;
    asm volatile("cp.async.cg.shared.global [%0], [%1], 16, %2;\n" :: "r"(saddr), "l"(g), "r"(sz));
}
__device__ __forceinline__ void ldm4(uint32_t* r, uint32_t addr){
    asm volatile("ldmatrix.sync.aligned.m8n8.x4.shared.b16 {%0,%1,%2,%3}, [%4];"
        : "=r"(r[0]),"=r"(r[1]),"=r"(r[2]),"=r"(r[3]) : "r"(addr));
}
__device__ __forceinline__ void ldm2(uint32_t* r, uint32_t addr){
    asm volatile("ldmatrix.sync.aligned.m8n8.x2.shared.b16 {%0,%1}, [%2];"
        : "=r"(r[0]),"=r"(r[1]) : "r"(addr));
}
__device__ __forceinline__ void ldm4t(uint32_t* r, uint32_t addr){
    asm volatile("ldmatrix.sync.aligned.m8n8.x4.trans.shared.b16 {%0,%1,%2,%3}, [%4];"
        : "=r"(r[0]),"=r"(r[1]),"=r"(r[2]),"=r"(r[3]) : "r"(addr));
}
__device__ __forceinline__ void mma16(float* c, const uint32_t* a, uint32_t b0, uint32_t b1){
    asm volatile(
      "mma.sync.aligned.m16n8k16.row.col.f32.f16.f16.f32 "
      "{%0,%1,%2,%3},{%4,%5,%6,%7},{%8,%9},{%0,%1,%2,%3};\n"
      : "+f"(c[0]), "+f"(c[1]), "+f"(c[2]), "+f"(c[3])
      : "r"(a[0]), "r"(a[1]), "r"(a[2]), "r"(a[3]), "r"(b0), "r"(b1));
}
__device__ __forceinline__ uint32_t frag_addr(uint32_t tile, int row0, int k0, int lane){
    int r = row0 + (lane & 7) + ((lane >> 3) & 1) * 8;
    int c = k0 + ((lane >> 4) << 3);
    return tile + SWZ((uint32_t)(r * 128 + c * 2));
}

// ---------------------------------------------------------------------------
// fp32 -> fp16 conversion prepass, single launch.
// blocks [0, 4096): x -> x_h.  blocks [4096, 6144): W sel -> w_h slab.
// ---------------------------------------------------------------------------
__global__ void __launch_bounds__(256)
conv_all(const float* __restrict__ x,
         const float* __restrict__ w0, const float* __restrict__ w1,
         const float* __restrict__ w2, const float* __restrict__ w3)
{
    const int bid = blockIdx.x;
    const float* src;
    __half* dst;
    int i;
    if (bid < 4096){
        src = x; dst = x_h;
        i = bid * 256 + threadIdx.x;
    } else {
        const int sel = (bid - 4096) >> 9;
        src = (sel==0) ? w0 : (sel==1 ? w1 : (sel==2 ? w2 : w3));
        dst = w_h + (size_t)sel * (HID*HID);
        i = ((bid - 4096) & 511) * 256 + threadIdx.x;
    }
    float4 v0 = ((const float4*)src)[2*i];
    float4 v1 = ((const float4*)src)[2*i+1];
    __half2 h0 = __floats2half2_rn(v0.x, v0.y);
    __half2 h1 = __floats2half2_rn(v0.z, v0.w);
    __half2 h2 = __floats2half2_rn(v1.x, v1.y);
    __half2 h3 = __floats2half2_rn(v1.z, v1.w);
    uint2 o0, o1;
    o0.x = *(uint32_t*)&h0; o0.y = *(uint32_t*)&h1;
    o1.x = *(uint32_t*)&h2; o1.y = *(uint32_t*)&h3;
    ((uint2*)dst)[2*i]   = o0;
    ((uint2*)dst)[2*i+1] = o1;
}

// ---------------------------------------------------------------------------
// fp16 GEMM:  Y[M,N] = A[M,K] @ W[N,K]^T + bias  (proven-fastest config)
// BM=128 BN=128 BK=64, 256 threads (8 warps, 4m x 2n), 2 CTAs/SM,
// 3-stage cp.async, SW128 smem, ldmatrix + mma.m16n8k16, 1 barrier/chunk.
// ---------------------------------------------------------------------------
#define GBK 64
#define A_BYT (128*128)         // 16 KB
#define STG   (2*A_BYT)         // 32 KB per stage
#define NSTG  3
#define NK    (HID/GBK)         // 16

__global__ void __launch_bounds__(256, 2)
gemm_h(const __half* __restrict__ A,
       const float* __restrict__ b0_, const float* __restrict__ b1_,
       const float* __restrict__ b2_, float* __restrict__ Yout, int qkv_mode)
{
    extern __shared__ char smem[];
    const uint32_t sb0 = smem_u32(smem);
    const int tid = threadIdx.x, lane = tid & 31, warp = tid >> 5;
    const int wm = warp & 3, wn = warp >> 2;            // 4m x 2n warps
    const int n0 = blockIdx.x * 128, m0 = blockIdx.y * 128;
    const int z  = qkv_mode ? blockIdx.z : 3;
    const __half* W    = w_h + (size_t)z * (HID*HID);
    const float* bias  = qkv_mode ? (z==0 ? b0_ : (z==1 ? b1_ : b2_)) : b0_;
    __half* dsth       = qkv_mode ? (z==0 ? q_d : (z==1 ? k_d : v_d)) : nullptr;

    float c[2][8][4];
    #pragma unroll
    for (int i = 0; i < 2; i++)
      #pragma unroll
      for (int j = 0; j < 8; j++)
        #pragma unroll
        for (int v = 0; v < 4; v++) c[i][j][v] = 0.f;

    auto load_chunk = [&](int ch, int slot){
        const int k0 = ch * GBK;
        const uint32_t uA = sb0 + slot * STG;
        const uint32_t uB = uA + A_BYT;
        #pragma unroll
        for (int i = 0; i < 4; i++){                    // A: 1024 16B ops
            int op = tid + i * 256;
            int row = op >> 3, at = op & 7;
            cp16s(uA + SWZ((uint32_t)(row * 128 + at * 16)),
                  A + (size_t)(m0 + row) * HID + k0 + at * 8);
        }
        #pragma unroll
        for (int i = 0; i < 4; i++){                    // B: 1024 16B ops
            int op = tid + i * 256;
            int row = op >> 3, at = op & 7;
            cp16s(uB + SWZ((uint32_t)(row * 128 + at * 16)),
                  W + (size_t)(n0 + row) * HID + k0 + at * 8);
        }
        asm volatile("cp.async.commit_group;\n");
    };

    load_chunk(0, 0);
    load_chunk(1, 1);

    for (int ch = 0; ch < NK; ch++){
        if (ch < NK - 1) asm volatile("cp.async.wait_group 1;\n");
        else             asm volatile("cp.async.wait_group 0;\n");
        __syncthreads();
        if (ch + 2 < NK) load_chunk(ch + 2, (ch + 2) % NSTG);

        const uint32_t uA = sb0 + (ch % NSTG) * STG;
        const uint32_t uB = uA + A_BYT;
        #pragma unroll
        for (int ks = 0; ks < 4; ks++){
            uint32_t a[2][4];
            ldm4(a[0], frag_addr(uA, wm*32,      ks*16, lane));
            ldm4(a[1], frag_addr(uA, wm*32 + 16, ks*16, lane));
            uint32_t b[4][4];
            #pragma unroll
            for (int nb = 0; nb < 4; nb++)
                ldm4(b[nb], frag_addr(uB, wn*64 + nb*16, ks*16, lane));
            #pragma unroll
            for (int nt = 0; nt < 8; nt++){
                const int nb = nt >> 1, hi = nt & 1;
                mma16(c[0][nt], a[0], b[nb][hi], b[nb][2+hi]);
                mma16(c[1][nt], a[1], b[nb][hi], b[nb][2+hi]);
            }
        }
    }
    __syncthreads();    // all compute done before staging buffer reuse

    if (qkv_mode){
        // staged epilogue: frags -> smem (half) -> fully coalesced 16B stores
        __half* stg = (__half*)smem;                    // 128 x 136 halves
        #pragma unroll
        for (int nt = 0; nt < 8; nt++){
            const int cn = wn*64 + nt*8 + 2*(lane & 3);
            float2 bv = *(const float2*)(bias + n0 + cn);
            #pragma unroll
            for (int mt = 0; mt < 2; mt++){
                const int r0 = wm*32 + mt*16 + (lane >> 2);
                #pragma unroll
                for (int hf = 0; hf < 2; hf++){
                    *(__half2*)&stg[(r0 + hf*8) * 136 + cn] =
                        __floats2half2_rn(c[mt][nt][hf*2] + bv.x,
                                          c[mt][nt][hf*2+1] + bv.y);
                }
            }
        }
        __syncthreads();
        #pragma unroll
        for (int i = 0; i < 8; i++){                    // 2048 16B slots
            int op = tid + i * 256;
            int row = op >> 4, c16 = op & 15;
            uint4 val = *(const uint4*)&stg[row * 136 + c16 * 8];
            *(uint4*)(dsth + (size_t)(m0 + row) * HID + n0 + c16 * 8) = val;
        }
    } else {
        #pragma unroll
        for (int nt = 0; nt < 8; nt++){
            const int nn = n0 + wn*64 + nt*8 + 2*(lane & 3);
            float2 bv = *(const float2*)(bias + nn);
            #pragma unroll
            for (int mt = 0; mt < 2; mt++){
                const int rr = m0 + wm*32 + mt*16 + (lane >> 2);
                #pragma unroll
                for (int hf = 0; hf < 2; hf++){
                    const int m = rr + hf*8;
                    *(float2*)(Yout + (size_t)m * HID + nn) =
                        make_float2(c[mt][nt][hf*2] + bv.x, c[mt][nt][hf*2+1] + bv.y);
                }
            }
        }
    }
}

// ---------------------------------------------------------------------------
// Fused attention: grid (34, NH, NB), 256 threads.
//   t in [0,32): band tile of 64 rows (R13 band code).
//   t in {32,33}: global rows 2*(t-32), 2*(t-32)+1 — FAST coalesced pattern
//                 (R12 access patterns at 256 threads; 2 rows share K/V reads).
//                 These 128 blocks are early in bid order and hide under the
//                 2048 band blocks' makespan.
// ---------------------------------------------------------------------------
#define PS_STR 168
#define QS_OFF 0
#define KS_OFF 8192
#define VS_OFF 26624
#define PS_OFF 45056
#define RED_OFF 66560
#define ATT_SMEM (RED_OFF + 1024)

__global__ void __launch_bounds__(256, 3)
attn_fused()
{
    extern __shared__ char smem[];
    const int tid = threadIdx.x;
    const int t = blockIdx.x, h = blockIdx.y, b = blockIdx.z;
    const size_t rbase = (size_t)b * SEQ * HID + h * HD;   // + s*HID + d

    if (t >= 32){
        // ================= global rows (fast path) =================
        float* qsf = (float*)smem;           // [2][64]
        float* s0  = qsf + 128;              // [2048]
        float* s1  = s0 + 2048;              // [2048]
        float* red = s1 + 2048;              // [256]
        float2* red2 = (float2*)(red + 256); // [256]
        const int r0 = 2 * (t - 32);

        if (tid < 128)
            qsf[tid] = __half2float(q_d[rbase + (size_t)(r0 + (tid >> 6)) * HID + (tid & 63)]);
        __syncthreads();

        // ---- QK: 8 threads per j (coalesced uint4), 32 j/pass, both rows ----
        const int sub = tid & 7, jof = tid >> 3;
        float qa[8], qb[8];
        #pragma unroll
        for (int i = 0; i < 8; i++){
            qa[i] = qsf[sub * 8 + i];
            qb[i] = qsf[64 + sub * 8 + i];
        }
        #pragma unroll 4
        for (int pass = 0; pass < 64; pass++){
            const int j = pass * 32 + jof;
            const uint4 kv4 = *(const uint4*)(k_d + rbase + (size_t)j * HID + sub * 8);
            const __half2* kh = (const __half2*)&kv4;
            float a0 = 0.f, a1 = 0.f;
            #pragma unroll
            for (int i = 0; i < 4; i++){
                float2 kf = __half22float2(kh[i]);
                a0 += qa[2*i] * kf.x + qa[2*i+1] * kf.y;
                a1 += qb[2*i] * kf.x + qb[2*i+1] * kf.y;
            }
            a0 += __shfl_xor_sync(0xffffffffu, a0, 1);
            a0 += __shfl_xor_sync(0xffffffffu, a0, 2);
            a0 += __shfl_xor_sync(0xffffffffu, a0, 4);
            a1 += __shfl_xor_sync(0xffffffffu, a1, 1);
            a1 += __shfl_xor_sync(0xffffffffu, a1, 2);
            a1 += __shfl_xor_sync(0xffffffffu, a1, 4);
            if (sub == 0){ s0[j] = a0 * ATT_SCALE; s1[j] = a1 * ATT_SCALE; }
        }
        __syncthreads();

        // ---- softmax per row (256-thread trees) ----
        float ri[2];
        #pragma unroll
        for (int rr = 0; rr < 2; rr++){
            float* s = rr ? s1 : s0;
            float lm = NEG;
            for (int j = tid; j < SEQ; j += 256) lm = fmaxf(lm, s[j]);
            red[tid] = lm; __syncthreads();
            for (int off = 128; off; off >>= 1){
                if (tid < off) red[tid] = fmaxf(red[tid], red[tid + off]);
                __syncthreads();
            }
            const float mx = red[0]; __syncthreads();

            float ls = 0.f;
            for (int j = tid; j < SEQ; j += 256){
                float p = __expf(s[j] - mx); s[j] = p; ls += p;
            }
            red[tid] = ls; __syncthreads();
            for (int off = 128; off; off >>= 1){
                if (tid < off) red[tid] += red[tid + off];
                __syncthreads();
            }
            ri[rr] = 1.f / red[0]; __syncthreads();
        }

        // ---- PV: coalesced half2 loads; both rows share V read ----
        const int dp = tid & 31, ch = tid >> 5;
        float2 acc0 = make_float2(0.f, 0.f), acc1 = acc0;
        const __half2* vb = (const __half2*)(v_d + rbase) + dp;
        #pragma unroll 8
        for (int j = ch * 256; j < ch * 256 + 256; j++){
            float2 vv = __half22float2(vb[(size_t)j * (HID/2)]);
            acc0.x += s0[j] * vv.x; acc0.y += s0[j] * vv.y;
            acc1.x += s1[j] * vv.x; acc1.y += s1[j] * vv.y;
        }
        red2[tid] = acc0; __syncthreads();
        if (tid < 32){
            float2 tot = red2[tid];
            #pragma unroll
            for (int cc = 1; cc < 8; cc++){
                float2 p = red2[cc * 32 + tid];
                tot.x += p.x; tot.y += p.y;
            }
            *(__half2*)(att_d + rbase + (size_t)r0 * HID + 2 * tid) =
                __floats2half2_rn(tot.x * ri[0], tot.y * ri[0]);
        }
        __syncthreads();
        red2[tid] = acc1; __syncthreads();
        if (tid < 32){
            float2 tot = red2[tid];
            #pragma unroll
            for (int cc = 1; cc < 8; cc++){
                float2 p = red2[cc * 32 + tid];
                tot.x += p.x; tot.y += p.y;
            }
            *(__half2*)(att_d + rbase + (size_t)(r0 + 1) * HID + 2 * tid) =
                __floats2half2_rn(tot.x * ri[1], tot.y * ri[1]);
        }
        return;
    }

    // ================= band tile path (R13) =================
    const uint32_t sb = smem_u32(smem);
    const uint32_t uQ = sb + QS_OFF, uK = sb + KS_OFF, uV = sb + VS_OFF;
    __half* Ps  = (__half*)(smem + PS_OFF);
    float* mred = (float*)(smem + RED_OFF);      // [2][64]
    float* sred = mred + 128;                    // [2][64]

    const int lane = tid & 31, warp = tid >> 5;
    const int q = lane & 3;
    const int i0 = t * 64;
    const int nglob = (t == 0) ? 0 : 4;
    const int jlo   = (t == 0) ? 0 : (i0 - 32);
    const int jhi   = min(SEQ - 1, i0 + 95);
    const int NC    = nglob + (jhi - jlo + 1);

    #pragma unroll
    for (int i = 0; i < 2; i++){
        int op = tid + i * 256;
        int row = op >> 3, at = op & 7;
        cp16s(uQ + SWZ((uint32_t)(row * 128 + at * 16)),
              q_d + rbase + (size_t)(i0 + row) * HID + at * 8);
    }
    #pragma unroll
    for (int i = 0; i < 9; i++){
        int op = tid + i * 256;
        int cc = op >> 4, at8 = op & 15;
        int at = at8 & 7;
        int isK = (at8 < 8);
        int valid = (cc < NC);
        int j = valid ? ((cc < nglob) ? cc : jlo + (cc - nglob)) : 0;
        const __half* src = (isK ? k_d : v_d) + rbase + (size_t)j * HID + at * 8;
        cp16z((isK ? uK : uV) + SWZ((uint32_t)(cc * 128 + at * 16)), src, valid);
    }
    asm volatile("cp.async.commit_group;\ncp.async.wait_group 0;\n");
    __syncthreads();

    // ---- scores ----
    {
        const int wm = warp >> 1, wn = warp & 1;
        const int r_lo = wm*16 + (lane >> 2);
        const int off_lo = (t == 0) ? (r_lo - 32) : (r_lo + 4);
        float cs[9][4];
        #pragma unroll
        for (int nt = 0; nt < 9; nt++)
            #pragma unroll
            for (int v = 0; v < 4; v++) cs[nt][v] = 0.f;

        #pragma unroll
        for (int ks = 0; ks < 4; ks++){
            uint32_t qa[4];
            ldm4(qa, frag_addr(uQ, wm*16, ks*16, lane));
            uint32_t kb[4][4];
            #pragma unroll
            for (int nb = 0; nb < 4; nb++)
                ldm4(kb[nb], frag_addr(uK, wn*72 + nb*16, ks*16, lane));
            uint32_t k2[2];
            {
                int i2 = lane & 15;
                int rr = wn*72 + 64 + (i2 & 7);
                int cc = ks*16 + ((i2 >> 3) << 3);
                ldm2(k2, uK + SWZ((uint32_t)(rr * 128 + cc * 2)));
            }
            #pragma unroll
            for (int nt = 0; nt < 8; nt++){
                const int nb = nt >> 1, hi = nt & 1;
                mma16(cs[nt], qa, kb[nb][hi], kb[nb][2+hi]);
            }
            mma16(cs[8], qa, k2[0], k2[1]);
        }

        // mask + scale in regs
        #pragma unroll
        for (int nt = 0; nt < 9; nt++)
            #pragma unroll
            for (int v = 0; v < 4; v++){
                const int cc  = wn*72 + nt*8 + 2*q + (v & 1);
                const int off = off_lo + ((v >= 2) ? 8 : 0);
                const bool ok = (cc < NC) &&
                                ((cc < 4) || ((unsigned)(cc - off) <= 64u));
                cs[nt][v] = ok ? cs[nt][v] * ATT_SCALE : NEG;
            }

        float mlo = NEG, mhi = NEG;
        #pragma unroll
        for (int nt = 0; nt < 9; nt++){
            mlo = fmaxf(mlo, fmaxf(cs[nt][0], cs[nt][1]));
            mhi = fmaxf(mhi, fmaxf(cs[nt][2], cs[nt][3]));
        }
        mlo = fmaxf(mlo, __shfl_xor_sync(0xffffffffu, mlo, 1));
        mlo = fmaxf(mlo, __shfl_xor_sync(0xffffffffu, mlo, 2));
        mhi = fmaxf(mhi, __shfl_xor_sync(0xffffffffu, mhi, 1));
        mhi = fmaxf(mhi, __shfl_xor_sync(0xffffffffu, mhi, 2));
        if (q == 0){
            mred[wn*64 + r_lo]     = mlo;
            mred[wn*64 + r_lo + 8] = mhi;
        }
        __syncthreads();
        mlo = fmaxf(mred[r_lo],     mred[64 + r_lo]);
        mhi = fmaxf(mred[r_lo + 8], mred[64 + r_lo + 8]);

        float slo = 0.f, shi = 0.f;
        #pragma unroll
        for (int nt = 0; nt < 9; nt++){
            const int cc0 = wn*72 + nt*8 + 2*q;
            float p0 = __expf(cs[nt][0] - mlo);
            float p1 = __expf(cs[nt][1] - mlo);
            float p2 = __expf(cs[nt][2] - mhi);
            float p3 = __expf(cs[nt][3] - mhi);
            slo += p0 + p1; shi += p2 + p3;
            *(__half2*)&Ps[(r_lo    ) * PS_STR + cc0] = __floats2half2_rn(p0, p1);
            *(__half2*)&Ps[(r_lo + 8) * PS_STR + cc0] = __floats2half2_rn(p2, p3);
        }
        slo += __shfl_xor_sync(0xffffffffu, slo, 1);
        slo += __shfl_xor_sync(0xffffffffu, slo, 2);
        shi += __shfl_xor_sync(0xffffffffu, shi, 1);
        shi += __shfl_xor_sync(0xffffffffu, shi, 2);
        if (q == 0){
            sred[wn*64 + r_lo]     = slo;
            sred[wn*64 + r_lo + 8] = shi;
        }
    }
    __syncthreads();

    // ---- PV ----
    {
        const int wm2 = warp >> 1, wn2 = warp & 1;
        const int r_lo = wm2*16 + (lane >> 2);
        float co[4][4];
        #pragma unroll
        for (int nt = 0; nt < 4; nt++)
            #pragma unroll
            for (int v = 0; v < 4; v++) co[nt][v] = 0.f;

        #pragma unroll
        for (int ks = 0; ks < 9; ks++){
            const int k0 = ks * 16;
            uint32_t pa[4];
            pa[0] = *(const uint32_t*)&Ps[(r_lo    ) * PS_STR + k0 + 2*q];
            pa[1] = *(const uint32_t*)&Ps[(r_lo + 8) * PS_STR + k0 + 2*q];
            pa[2] = *(const uint32_t*)&Ps[(r_lo    ) * PS_STR + k0 + 8 + 2*q];
            pa[3] = *(const uint32_t*)&Ps[(r_lo + 8) * PS_STR + k0 + 8 + 2*q];
            uint32_t vb[2][4];
            #pragma unroll
            for (int db = 0; db < 2; db++){
                int m_ = lane >> 3;
                int j  = k0 + (lane & 7) + (m_ & 1) * 8;
                int dc = wn2*32 + db*16 + (m_ >> 1) * 8;
                ldm4t(vb[db], uV + SWZ((uint32_t)(j * 128 + dc * 2)));
            }
            #pragma unroll
            for (int nt = 0; nt < 4; nt++){
                const int db = nt >> 1, hi = nt & 1;
                mma16(co[nt], pa, vb[db][hi*2], vb[db][hi*2 + 1]);
            }
        }

        const float rlo = 1.f / (sred[r_lo]     + sred[64 + r_lo]);
        const float rhi = 1.f / (sred[r_lo + 8] + sred[64 + r_lo + 8]);
        #pragma unroll
        for (int nt = 0; nt < 4; nt++){
            const int d0 = wn2*32 + nt*8 + 2*q;
            #pragma unroll
            for (int hf = 0; hf < 2; hf++){
                const int r = r_lo + hf*8;
                const int i = i0 + r;
                if (i >= 4){
                    float sc = hf ? rhi : rlo;
                    __half2 hv = __floats2half2_rn(co[nt][hf*2] * sc, co[nt][hf*2+1] * sc);
                    *(__half2*)(att_d + rbase + (size_t)i * HID + d0) = hv;
                }
            }
        }
    }
}

// ---------------------------------------------------------------------------
extern "C" void kernel_launch(void* const* d_in, const int* in_sizes, int n_in,
                              void* d_out, int out_size)
{
    const float* x  = (const float*)d_in[0];
    const float* Wq = (const float*)d_in[1];
    const float* bq = (const float*)d_in[2];
    const float* Wk = (const float*)d_in[3];
    const float* bk = (const float*)d_in[4];
    const float* Wv = (const float*)d_in[5];
    const float* bv = (const float*)d_in[6];
    const float* Wo = (const float*)d_in[7];
    const float* bo = (const float*)d_in[8];
    float* out = (float*)d_out;

    const int gsm = NSTG * STG;     // 98304 B
    cudaFuncSetAttribute(gemm_h,     cudaFuncAttributeMaxDynamicSharedMemorySize, gsm);
    cudaFuncSetAttribute(attn_fused, cudaFuncAttributeMaxDynamicSharedMemorySize, ATT_SMEM);

    static __half* p_xh = nullptr;
    static __half* p_att = nullptr;
    if (!p_xh){
        void* tmp;
        cudaGetSymbolAddress(&tmp, x_h);   p_xh  = (__half*)tmp;
        cudaGetSymbolAddress(&tmp, att_d); p_att = (__half*)tmp;
    }

    // launch 0: all fp32->fp16 conversions
    conv_all<<<6144, 256>>>(x, Wq, Wk, Wv, Wo);
    // launch 1: fused QKV projections
    gemm_h<<<dim3(HID/128, MTOT/128, 3), 256, gsm>>>(p_xh, bq, bk, bv, nullptr, 1);
    // launch 2: fused attention (band tiles + global rows in one launch)
    attn_fused<<<dim3(34, NH, NB), 256, ATT_SMEM>>>();
    // launch 3: output projection
    gemm_h<<<dim3(HID/128, MTOT/128, 1), 256, gsm>>>(p_att, bo, nullptr, nullptr, out, 0);
}

// round 17
// speedup vs baseline: 1.0372x; 1.0372x over previous
#include <cuda_runtime.h>
#include <cuda_fp16.h>
#include <cstdint>

// R17: attention kernels reverted to the R13-passing pair (merge in R16
// regressed: global blocks' 67.6KB smem requests stole band occupancy).
// NEW: attn_global runs on a forked capture stream, overlapping attn_band.

#define SEQ 2048
#define NB 4
#define NH 16
#define HD 64
#define HID 1024
#define MTOT (NB*SEQ)
#define NEG -1e30f
#define ATT_SCALE 0.125f

// ---------------- scratch (device globals; allocation-free rule) ----------
__device__ __half q_d[(size_t)MTOT*HID];
__device__ __half k_d[(size_t)MTOT*HID];
__device__ __half v_d[(size_t)MTOT*HID];
__device__ __half att_d[(size_t)MTOT*HID];
__device__ __half x_h[(size_t)MTOT*HID];
__device__ __half w_h[4*(size_t)HID*HID];

// ---------------- helpers -------------------------------------------------
__device__ __forceinline__ uint32_t smem_u32(const void* p){
    uint32_t a;
    asm("{ .reg .u64 t; cvta.to.shared.u64 t, %1; cvt.u32.u64 %0, t; }" : "=r"(a) : "l"(p));
    return a;
}
#define SWZ(b) ((b) ^ (((b) >> 3) & 0x70))

__device__ __forceinline__ void cp16s(uint32_t saddr, const void* g){
    asm volatile("cp.async.cg.shared.global [%0], [%1], 16;\n" :: "r"(saddr), "l"(g));
}
__device__ __forceinline__ void cp16z(uint32_t saddr, const void* g, int pred){
    int sz = pred ? 16 : 0;
    asm volatile("cp.async.cg.shared.global [%0], [%1], 16, %2;\n" :: "r"(saddr), "l"(g), "r"(sz));
}
__device__ __forceinline__ void ldm4(uint32_t* r, uint32_t addr){
    asm volatile("ldmatrix.sync.aligned.m8n8.x4.shared.b16 {%0,%1,%2,%3}, [%4];"
        : "=r"(r[0]),"=r"(r[1]),"=r"(r[2]),"=r"(r[3]) : "r"(addr));
}
__device__ __forceinline__ void ldm2(uint32_t* r, uint32_t addr){
    asm volatile("ldmatrix.sync.aligned.m8n8.x2.shared.b16 {%0,%1}, [%2];"
        : "=r"(r[0]),"=r"(r[1]) : "r"(addr));
}
__device__ __forceinline__ void ldm4t(uint32_t* r, uint32_t addr){
    asm volatile("ldmatrix.sync.aligned.m8n8.x4.trans.shared.b16 {%0,%1,%2,%3}, [%4];"
        : "=r"(r[0]),"=r"(r[1]),"=r"(r[2]),"=r"(r[3]) : "r"(addr));
}
__device__ __forceinline__ void mma16(float* c, const uint32_t* a, uint32_t b0, uint32_t b1){
    asm volatile(
      "mma.sync.aligned.m16n8k16.row.col.f32.f16.f16.f32 "
      "{%0,%1,%2,%3},{%4,%5,%6,%7},{%8,%9},{%0,%1,%2,%3};\n"
      : "+f"(c[0]), "+f"(c[1]), "+f"(c[2]), "+f"(c[3])
      : "r"(a[0]), "r"(a[1]), "r"(a[2]), "r"(a[3]), "r"(b0), "r"(b1));
}
__device__ __forceinline__ uint32_t frag_addr(uint32_t tile, int row0, int k0, int lane){
    int r = row0 + (lane & 7) + ((lane >> 3) & 1) * 8;
    int c = k0 + ((lane >> 4) << 3);
    return tile + SWZ((uint32_t)(r * 128 + c * 2));
}

// ---------------------------------------------------------------------------
// fp32 -> fp16 conversion prepass, single launch.
// ---------------------------------------------------------------------------
__global__ void __launch_bounds__(256)
conv_all(const float* __restrict__ x,
         const float* __restrict__ w0, const float* __restrict__ w1,
         const float* __restrict__ w2, const float* __restrict__ w3)
{
    const int bid = blockIdx.x;
    const float* src;
    __half* dst;
    int i;
    if (bid < 4096){
        src = x; dst = x_h;
        i = bid * 256 + threadIdx.x;
    } else {
        const int sel = (bid - 4096) >> 9;
        src = (sel==0) ? w0 : (sel==1 ? w1 : (sel==2 ? w2 : w3));
        dst = w_h + (size_t)sel * (HID*HID);
        i = ((bid - 4096) & 511) * 256 + threadIdx.x;
    }
    float4 v0 = ((const float4*)src)[2*i];
    float4 v1 = ((const float4*)src)[2*i+1];
    __half2 h0 = __floats2half2_rn(v0.x, v0.y);
    __half2 h1 = __floats2half2_rn(v0.z, v0.w);
    __half2 h2 = __floats2half2_rn(v1.x, v1.y);
    __half2 h3 = __floats2half2_rn(v1.z, v1.w);
    uint2 o0, o1;
    o0.x = *(uint32_t*)&h0; o0.y = *(uint32_t*)&h1;
    o1.x = *(uint32_t*)&h2; o1.y = *(uint32_t*)&h3;
    ((uint2*)dst)[2*i]   = o0;
    ((uint2*)dst)[2*i+1] = o1;
}

// ---------------------------------------------------------------------------
// fp16 GEMM (proven-fastest config, R13): BM=BN=128 BK=64, 256 thr, 2 CTA/SM,
// 3-stage cp.async, SW128, ldmatrix + mma.m16n8k16, 1 barrier/chunk.
// ---------------------------------------------------------------------------
#define GBK 64
#define A_BYT (128*128)
#define STG   (2*A_BYT)
#define NSTG  3
#define NK    (HID/GBK)

__global__ void __launch_bounds__(256, 2)
gemm_h(const __half* __restrict__ A,
       const float* __restrict__ b0_, const float* __restrict__ b1_,
       const float* __restrict__ b2_, float* __restrict__ Yout, int qkv_mode)
{
    extern __shared__ char smem[];
    const uint32_t sb0 = smem_u32(smem);
    const int tid = threadIdx.x, lane = tid & 31, warp = tid >> 5;
    const int wm = warp & 3, wn = warp >> 2;
    const int n0 = blockIdx.x * 128, m0 = blockIdx.y * 128;
    const int z  = qkv_mode ? blockIdx.z : 3;
    const __half* W    = w_h + (size_t)z * (HID*HID);
    const float* bias  = qkv_mode ? (z==0 ? b0_ : (z==1 ? b1_ : b2_)) : b0_;
    __half* dsth       = qkv_mode ? (z==0 ? q_d : (z==1 ? k_d : v_d)) : nullptr;

    float c[2][8][4];
    #pragma unroll
    for (int i = 0; i < 2; i++)
      #pragma unroll
      for (int j = 0; j < 8; j++)
        #pragma unroll
        for (int v = 0; v < 4; v++) c[i][j][v] = 0.f;

    auto load_chunk = [&](int ch, int slot){
        const int k0 = ch * GBK;
        const uint32_t uA = sb0 + slot * STG;
        const uint32_t uB = uA + A_BYT;
        #pragma unroll
        for (int i = 0; i < 4; i++){
            int op = tid + i * 256;
            int row = op >> 3, at = op & 7;
            cp16s(uA + SWZ((uint32_t)(row * 128 + at * 16)),
                  A + (size_t)(m0 + row) * HID + k0 + at * 8);
        }
        #pragma unroll
        for (int i = 0; i < 4; i++){
            int op = tid + i * 256;
            int row = op >> 3, at = op & 7;
            cp16s(uB + SWZ((uint32_t)(row * 128 + at * 16)),
                  W + (size_t)(n0 + row) * HID + k0 + at * 8);
        }
        asm volatile("cp.async.commit_group;\n");
    };

    load_chunk(0, 0);
    load_chunk(1, 1);

    for (int ch = 0; ch < NK; ch++){
        if (ch < NK - 1) asm volatile("cp.async.wait_group 1;\n");
        else             asm volatile("cp.async.wait_group 0;\n");
        __syncthreads();
        if (ch + 2 < NK) load_chunk(ch + 2, (ch + 2) % NSTG);

        const uint32_t uA = sb0 + (ch % NSTG) * STG;
        const uint32_t uB = uA + A_BYT;
        #pragma unroll
        for (int ks = 0; ks < 4; ks++){
            uint32_t a[2][4];
            ldm4(a[0], frag_addr(uA, wm*32,      ks*16, lane));
            ldm4(a[1], frag_addr(uA, wm*32 + 16, ks*16, lane));
            uint32_t b[4][4];
            #pragma unroll
            for (int nb = 0; nb < 4; nb++)
                ldm4(b[nb], frag_addr(uB, wn*64 + nb*16, ks*16, lane));
            #pragma unroll
            for (int nt = 0; nt < 8; nt++){
                const int nb = nt >> 1, hi = nt & 1;
                mma16(c[0][nt], a[0], b[nb][hi], b[nb][2+hi]);
                mma16(c[1][nt], a[1], b[nb][hi], b[nb][2+hi]);
            }
        }
    }
    __syncthreads();

    if (qkv_mode){
        __half* stg = (__half*)smem;
        #pragma unroll
        for (int nt = 0; nt < 8; nt++){
            const int cn = wn*64 + nt*8 + 2*(lane & 3);
            float2 bv = *(const float2*)(bias + n0 + cn);
            #pragma unroll
            for (int mt = 0; mt < 2; mt++){
                const int r0 = wm*32 + mt*16 + (lane >> 2);
                #pragma unroll
                for (int hf = 0; hf < 2; hf++){
                    *(__half2*)&stg[(r0 + hf*8) * 136 + cn] =
                        __floats2half2_rn(c[mt][nt][hf*2] + bv.x,
                                          c[mt][nt][hf*2+1] + bv.y);
                }
            }
        }
        __syncthreads();
        #pragma unroll
        for (int i = 0; i < 8; i++){
            int op = tid + i * 256;
            int row = op >> 4, c16 = op & 15;
            uint4 val = *(const uint4*)&stg[row * 136 + c16 * 8];
            *(uint4*)(dsth + (size_t)(m0 + row) * HID + n0 + c16 * 8) = val;
        }
    } else {
        #pragma unroll
        for (int nt = 0; nt < 8; nt++){
            const int nn = n0 + wn*64 + nt*8 + 2*(lane & 3);
            float2 bv = *(const float2*)(bias + nn);
            #pragma unroll
            for (int mt = 0; mt < 2; mt++){
                const int rr = m0 + wm*32 + mt*16 + (lane >> 2);
                #pragma unroll
                for (int hf = 0; hf < 2; hf++){
                    const int m = rr + hf*8;
                    *(float2*)(Yout + (size_t)m * HID + nn) =
                        make_float2(c[mt][nt][hf*2] + bv.x, c[mt][nt][hf*2+1] + bv.y);
                }
            }
        }
    }
}

// ---------------------------------------------------------------------------
// Band attention (R13, measured ~33us): one block per (64-row tile, head, b).
// ---------------------------------------------------------------------------
#define PS_STR 168
#define QS_OFF 0
#define KS_OFF 8192
#define VS_OFF 26624
#define PS_OFF 45056
#define RED_OFF 66560
#define ATT_SMEM (RED_OFF + 1024)

__global__ void __launch_bounds__(256, 3)
attn_band()
{
    extern __shared__ char smem[];
    const uint32_t sb = smem_u32(smem);
    const uint32_t uQ = sb + QS_OFF, uK = sb + KS_OFF, uV = sb + VS_OFF;
    __half* Ps  = (__half*)(smem + PS_OFF);
    float* mred = (float*)(smem + RED_OFF);
    float* sred = mred + 128;

    const int tid = threadIdx.x, lane = tid & 31, warp = tid >> 5;
    const int q = lane & 3;
    const int t = blockIdx.x, h = blockIdx.y, b = blockIdx.z;
    const int i0 = t * 64;
    const int nglob = (t == 0) ? 0 : 4;
    const int jlo   = (t == 0) ? 0 : (i0 - 32);
    const int jhi   = min(SEQ - 1, i0 + 95);
    const int NC    = nglob + (jhi - jlo + 1);
    const size_t rbase = (size_t)b * SEQ * HID + h * HD;

    #pragma unroll
    for (int i = 0; i < 2; i++){
        int op = tid + i * 256;
        int row = op >> 3, at = op & 7;
        cp16s(uQ + SWZ((uint32_t)(row * 128 + at * 16)),
              q_d + rbase + (size_t)(i0 + row) * HID + at * 8);
    }
    #pragma unroll
    for (int i = 0; i < 9; i++){
        int op = tid + i * 256;
        int cc = op >> 4, at8 = op & 15;
        int at = at8 & 7;
        int isK = (at8 < 8);
        int valid = (cc < NC);
        int j = valid ? ((cc < nglob) ? cc : jlo + (cc - nglob)) : 0;
        const __half* src = (isK ? k_d : v_d) + rbase + (size_t)j * HID + at * 8;
        cp16z((isK ? uK : uV) + SWZ((uint32_t)(cc * 128 + at * 16)), src, valid);
    }
    asm volatile("cp.async.commit_group;\ncp.async.wait_group 0;\n");
    __syncthreads();

    // ---- scores ----
    {
        const int wm = warp >> 1, wn = warp & 1;
        const int r_lo = wm*16 + (lane >> 2);
        const int off_lo = (t == 0) ? (r_lo - 32) : (r_lo + 4);
        float cs[9][4];
        #pragma unroll
        for (int nt = 0; nt < 9; nt++)
            #pragma unroll
            for (int v = 0; v < 4; v++) cs[nt][v] = 0.f;

        #pragma unroll
        for (int ks = 0; ks < 4; ks++){
            uint32_t qa[4];
            ldm4(qa, frag_addr(uQ, wm*16, ks*16, lane));
            uint32_t kb[4][4];
            #pragma unroll
            for (int nb = 0; nb < 4; nb++)
                ldm4(kb[nb], frag_addr(uK, wn*72 + nb*16, ks*16, lane));
            uint32_t k2[2];
            {
                int i2 = lane & 15;
                int rr = wn*72 + 64 + (i2 & 7);
                int cc = ks*16 + ((i2 >> 3) << 3);
                ldm2(k2, uK + SWZ((uint32_t)(rr * 128 + cc * 2)));
            }
            #pragma unroll
            for (int nt = 0; nt < 8; nt++){
                const int nb = nt >> 1, hi = nt & 1;
                mma16(cs[nt], qa, kb[nb][hi], kb[nb][2+hi]);
            }
            mma16(cs[8], qa, k2[0], k2[1]);
        }

        #pragma unroll
        for (int nt = 0; nt < 9; nt++)
            #pragma unroll
            for (int v = 0; v < 4; v++){
                const int cc  = wn*72 + nt*8 + 2*q + (v & 1);
                const int off = off_lo + ((v >= 2) ? 8 : 0);
                const bool ok = (cc < NC) &&
                                ((cc < 4) || ((unsigned)(cc - off) <= 64u));
                cs[nt][v] = ok ? cs[nt][v] * ATT_SCALE : NEG;
            }

        float mlo = NEG, mhi = NEG;
        #pragma unroll
        for (int nt = 0; nt < 9; nt++){
            mlo = fmaxf(mlo, fmaxf(cs[nt][0], cs[nt][1]));
            mhi = fmaxf(mhi, fmaxf(cs[nt][2], cs[nt][3]));
        }
        mlo = fmaxf(mlo, __shfl_xor_sync(0xffffffffu, mlo, 1));
        mlo = fmaxf(mlo, __shfl_xor_sync(0xffffffffu, mlo, 2));
        mhi = fmaxf(mhi, __shfl_xor_sync(0xffffffffu, mhi, 1));
        mhi = fmaxf(mhi, __shfl_xor_sync(0xffffffffu, mhi, 2));
        if (q == 0){
            mred[wn*64 + r_lo]     = mlo;
            mred[wn*64 + r_lo + 8] = mhi;
        }
        __syncthreads();
        mlo = fmaxf(mred[r_lo],     mred[64 + r_lo]);
        mhi = fmaxf(mred[r_lo + 8], mred[64 + r_lo + 8]);

        float slo = 0.f, shi = 0.f;
        #pragma unroll
        for (int nt = 0; nt < 9; nt++){
            const int cc0 = wn*72 + nt*8 + 2*q;
            float p0 = __expf(cs[nt][0] - mlo);
            float p1 = __expf(cs[nt][1] - mlo);
            float p2 = __expf(cs[nt][2] - mhi);
            float p3 = __expf(cs[nt][3] - mhi);
            slo += p0 + p1; shi += p2 + p3;
            *(__half2*)&Ps[(r_lo    ) * PS_STR + cc0] = __floats2half2_rn(p0, p1);
            *(__half2*)&Ps[(r_lo + 8) * PS_STR + cc0] = __floats2half2_rn(p2, p3);
        }
        slo += __shfl_xor_sync(0xffffffffu, slo, 1);
        slo += __shfl_xor_sync(0xffffffffu, slo, 2);
        shi += __shfl_xor_sync(0xffffffffu, shi, 1);
        shi += __shfl_xor_sync(0xffffffffu, shi, 2);
        if (q == 0){
            sred[wn*64 + r_lo]     = slo;
            sred[wn*64 + r_lo + 8] = shi;
        }
    }
    __syncthreads();

    // ---- PV ----
    {
        const int wm2 = warp >> 1, wn2 = warp & 1;
        const int r_lo = wm2*16 + (lane >> 2);
        float co[4][4];
        #pragma unroll
        for (int nt = 0; nt < 4; nt++)
            #pragma unroll
            for (int v = 0; v < 4; v++) co[nt][v] = 0.f;

        #pragma unroll
        for (int ks = 0; ks < 9; ks++){
            const int k0 = ks * 16;
            uint32_t pa[4];
            pa[0] = *(const uint32_t*)&Ps[(r_lo    ) * PS_STR + k0 + 2*q];
            pa[1] = *(const uint32_t*)&Ps[(r_lo + 8) * PS_STR + k0 + 2*q];
            pa[2] = *(const uint32_t*)&Ps[(r_lo    ) * PS_STR + k0 + 8 + 2*q];
            pa[3] = *(const uint32_t*)&Ps[(r_lo + 8) * PS_STR + k0 + 8 + 2*q];
            uint32_t vb[2][4];
            #pragma unroll
            for (int db = 0; db < 2; db++){
                int m_ = lane >> 3;
                int j  = k0 + (lane & 7) + (m_ & 1) * 8;
                int dc = wn2*32 + db*16 + (m_ >> 1) * 8;
                ldm4t(vb[db], uV + SWZ((uint32_t)(j * 128 + dc * 2)));
            }
            #pragma unroll
            for (int nt = 0; nt < 4; nt++){
                const int db = nt >> 1, hi = nt & 1;
                mma16(co[nt], pa, vb[db][hi*2], vb[db][hi*2 + 1]);
            }
        }

        const float rlo = 1.f / (sred[r_lo]     + sred[64 + r_lo]);
        const float rhi = 1.f / (sred[r_lo + 8] + sred[64 + r_lo + 8]);
        #pragma unroll
        for (int nt = 0; nt < 4; nt++){
            const int d0 = wn2*32 + nt*8 + 2*q;
            #pragma unroll
            for (int hf = 0; hf < 2; hf++){
                const int r = r_lo + hf*8;
                const int i = i0 + r;
                if (i >= 4){
                    float sc = hf ? rhi : rlo;
                    __half2 hv = __floats2half2_rn(co[nt][hf*2] * sc, co[nt][hf*2+1] * sc);
                    *(__half2*)(att_d + rbase + (size_t)i * HID + d0) = hv;
                }
            }
        }
    }
}

// ---------------------------------------------------------------------------
// Global rows (i < 4): 256 blocks x 1024 threads (R12/R13, measured 20.7us).
// ---------------------------------------------------------------------------
__global__ void __launch_bounds__(1024)
attn_global()
{
    __shared__ float qs[HD];
    __shared__ float s[SEQ];
    __shared__ float red[1024];
    __shared__ float2 red2[1024];
    const int tid = threadIdx.x;
    const int r = blockIdx.x, h = blockIdx.y, b = blockIdx.z;
    const size_t rbase = (size_t)b * SEQ * HID + h * HD;

    if (tid < HD) qs[tid] = __half2float(q_d[rbase + (size_t)r * HID + tid]);
    __syncthreads();

    const int sub = tid & 7;
    const int jof = tid >> 3;
    float qreg[8];
    #pragma unroll
    for (int i = 0; i < 8; i++) qreg[i] = qs[sub * 8 + i];

    #pragma unroll 4
    for (int pass = 0; pass < 16; pass++){
        const int j = pass * 128 + jof;
        const uint4 kv4 = *(const uint4*)(k_d + rbase + (size_t)j * HID + sub * 8);
        const __half2* kh = (const __half2*)&kv4;
        float acc = 0.f;
        #pragma unroll
        for (int i = 0; i < 4; i++){
            float2 kf = __half22float2(kh[i]);
            acc += qreg[2*i] * kf.x + qreg[2*i+1] * kf.y;
        }
        acc += __shfl_xor_sync(0xffffffffu, acc, 1);
        acc += __shfl_xor_sync(0xffffffffu, acc, 2);
        acc += __shfl_xor_sync(0xffffffffu, acc, 4);
        if (sub == 0) s[j] = acc * ATT_SCALE;
    }
    __syncthreads();

    float lm = fmaxf(s[tid], s[tid + 1024]);
    red[tid] = lm; __syncthreads();
    for (int off = 512; off; off >>= 1){
        if (tid < off) red[tid] = fmaxf(red[tid], red[tid + off]);
        __syncthreads();
    }
    const float mx = red[0]; __syncthreads();

    float ls = 0.f;
    #pragma unroll
    for (int jj = 0; jj < 2; jj++){
        const int j = tid + jj * 1024;
        float p = __expf(s[j] - mx); s[j] = p; ls += p;
    }
    red[tid] = ls; __syncthreads();
    for (int off = 512; off; off >>= 1){
        if (tid < off) red[tid] += red[tid + off];
        __syncthreads();
    }
    const float ri = 1.f / red[0]; __syncthreads();

    const int dp = tid & 31;
    const int ch = tid >> 5;
    float2 acc2 = make_float2(0.f, 0.f);
    const __half2* vb = (const __half2*)(v_d + rbase) + dp;
    #pragma unroll 8
    for (int j = ch * 64; j < ch * 64 + 64; j++){
        float2 vv = __half22float2(vb[(size_t)j * (HID/2)]);
        const float sv = s[j];
        acc2.x += sv * vv.x;
        acc2.y += sv * vv.y;
    }
    red2[tid] = acc2; __syncthreads();
    if (tid < 32){
        float2 tot = red2[tid];
        #pragma unroll
        for (int cc = 1; cc < 32; cc++){
            float2 p = red2[cc * 32 + tid];
            tot.x += p.x; tot.y += p.y;
        }
        *(__half2*)(att_d + rbase + (size_t)r * HID + 2 * tid) =
            __floats2half2_rn(tot.x * ri, tot.y * ri);
    }
}

// ---------------------------------------------------------------------------
extern "C" void kernel_launch(void* const* d_in, const int* in_sizes, int n_in,
                              void* d_out, int out_size)
{
    const float* x  = (const float*)d_in[0];
    const float* Wq = (const float*)d_in[1];
    const float* bq = (const float*)d_in[2];
    const float* Wk = (const float*)d_in[3];
    const float* bk = (const float*)d_in[4];
    const float* Wv = (const float*)d_in[5];
    const float* bv = (const float*)d_in[6];
    const float* Wo = (const float*)d_in[7];
    const float* bo = (const float*)d_in[8];
    float* out = (float*)d_out;

    const int gsm = NSTG * STG;     // 98304 B
    cudaFuncSetAttribute(gemm_h,    cudaFuncAttributeMaxDynamicSharedMemorySize, gsm);
    cudaFuncSetAttribute(attn_band, cudaFuncAttributeMaxDynamicSharedMemorySize, ATT_SMEM);

    static __half* p_xh = nullptr;
    static __half* p_att = nullptr;
    static cudaStream_t s2 = nullptr;
    static cudaEvent_t evA = nullptr, evB = nullptr;
    if (!p_xh){
        void* tmp;
        cudaGetSymbolAddress(&tmp, x_h);   p_xh  = (__half*)tmp;
        cudaGetSymbolAddress(&tmp, att_d); p_att = (__half*)tmp;
        cudaStreamCreateWithFlags(&s2, cudaStreamNonBlocking);
        cudaEventCreateWithFlags(&evA, cudaEventDisableTiming);
        cudaEventCreateWithFlags(&evB, cudaEventDisableTiming);
    }

    // launch 0: all fp32->fp16 conversions (main/capture stream)
    conv_all<<<6144, 256>>>(x, Wq, Wk, Wv, Wo);
    // launch 1: fused QKV projections (main stream)
    gemm_h<<<dim3(HID/128, MTOT/128, 3), 256, gsm>>>(p_xh, bq, bk, bv, nullptr, 1);

    // fork: attn_global on side stream, concurrent with attn_band on main
    cudaEventRecord(evA, 0);
    cudaStreamWaitEvent(s2, evA, 0);
    attn_global<<<dim3(4, NH, NB), 1024, 0, s2>>>();
    cudaEventRecord(evB, s2);

    attn_band<<<dim3(SEQ/64, NH, NB), 256, ATT_SMEM>>>();

    // join: O-GEMM needs both attention kernels complete
    cudaStreamWaitEvent(0, evB, 0);
    gemm_h<<<dim3(HID/128, MTOT/128, 1), 256, gsm>>>(p_att, bo, nullptr, nullptr, out, 0);
}